// round 9
// baseline (speedup 1.0000x reference)
#include <cuda_runtime.h>

// x: (64, 8, 32, 32) fp32. 1 center + 63 error rows, content = 8192 elements.
// Output = (1 + 63 + 8192) x 8192 = 270 MB.
#define N_CONTENT 8192
#define N_COL4    (N_CONTENT / 4)   // 2048
#define E_ROWS    64
#define NCHUNK    128               // prep chunks; 64 k's each
#define TOTAL_ROWS (E_ROWS + N_CONTENT)   // 8256

// Scratch (__device__ globals; no allocation allowed). Zero-init at load.
__device__ float4             g_mult4[N_COL4];
__device__ float4             g_head4[N_COL4];
__device__ int                g_col[N_CONTENT];     // tail row r -> column k
__device__ float              g_tval[N_CONTENT];    // tail row r -> delta/2
__device__ int                g_total;              // number of crossings
__device__ unsigned long long g_pub[NCHUNK];        // (epoch<<32)|count
__device__ unsigned           g_blkepoch[TOTAL_ROWS]; // per-block launch counter
__device__ unsigned           g_prep_ctr;           // monotone prep-completion count
__device__ volatile unsigned  g_done;               // = L when launch L's prep is done

// ---------------------------------------------------------------------------
// Single fused kernel: blocks 0..127 run prep for their 64-k chunk, then all
// blocks write their output row. Tail rows stream zeros before waiting.
// ---------------------------------------------------------------------------
__global__ void __launch_bounds__(256) fused_kernel(
        const float* __restrict__ x, float4* __restrict__ out4) {
    __shared__ unsigned s_L;
    int bid = blockIdx.x;
    int t   = threadIdx.x;

    // launch epoch: each block bumps its own counter exactly once per launch,
    // so every replay of the captured graph sees a consistent L everywhere.
    if (t == 0) {
        unsigned L = g_blkepoch[bid] + 1;
        g_blkepoch[bid] = L;
        s_L = L;
    }
    __syncthreads();
    unsigned L = s_L;

    // ======================= prep phase (blocks 0..127) ====================
    if (bid < NCHUNK) {
        __shared__ float    s_err[4][64];
        __shared__ unsigned s_mask[2];
        __shared__ int      s_excl;

        int kk = t & 63;
        int sl = t >> 6;                       // e-slice 0..3 (16 rows each)
        {
            int k  = bid * 64 + kk;
            int e0 = sl * 16 + (sl == 0 ? 1 : 0);   // skip center row
            int e1 = sl * 16 + 16;
            float p = 0.f;
#pragma unroll
            for (int e = e0; e < e1; e++)
                p += fabsf(x[e * N_CONTENT + k]);
            s_err[sl][kk] = p;
        }
        __syncthreads();

        int   flag = 0;
        float val  = 0.f;
        if (t < 64) {
            int k = bid * 64 + t;
            float err = s_err[0][t] + s_err[1][t] + s_err[2][t] + s_err[3][t];
            float c = x[k];

            float upper = c + err;
            float lower = c - err;

            float cross  = (lower * upper < 0.f) ? 1.f : 0.f;
            float nonneg = (lower >= 0.f) ? 1.f : 0.f;

            // Reference-exact: lam = nonneg + cross*upper/(upper-lower), NaN->0.5
            float lam = nonneg + cross * (upper / (upper - lower));
            if (isnan(lam)) lam = 0.5f;

            float delta = fmaxf(-lam * lower, (1.f - lam) * upper);

            ((float*)g_mult4)[k] = lam * cross + nonneg;
            ((float*)g_head4)[k] = (delta * 0.5f + lam * c) * cross + c * nonneg;

            flag = (cross > 0.f) ? 1 : 0;
            val  = delta * 0.5f;

            unsigned bal = __ballot_sync(0xffffffffu, flag);
            if ((t & 31) == 0) s_mask[t >> 5] = bal;
        }
        __syncthreads();

        int cnt = __popc(s_mask[0]) + __popc(s_mask[1]);

        // publish (epoch, count) for the cross-block exclusive prefix
        if (t == 0)
            atomicExch(&g_pub[bid], ((unsigned long long)L << 32) | (unsigned)cnt);

        // warp 0 sums predecessor counts (32-wide overlapped polling)
        if (t < 32) {
            int sum = 0;
            for (int i = t; i < bid; i += 32) {
                unsigned long long w2;
                do {
                    w2 = *((volatile unsigned long long*)&g_pub[i]);
                } while ((unsigned)(w2 >> 32) != L);
                sum += (int)(w2 & 0xffffffffu);
            }
#pragma unroll
            for (int off = 16; off > 0; off >>= 1)
                sum += __shfl_down_sync(0xffffffffu, sum, off);
            if (t == 0) s_excl = sum;
        }
        __syncthreads();
        int excl = s_excl;

        if (t < 64 && flag) {
            unsigned m0 = s_mask[0], m1 = s_mask[1];
            int rank = (t < 32) ? __popc(m0 & ((1u << t) - 1u))
                                : __popc(m0) + __popc(m1 & ((1u << (t - 32)) - 1u));
            int r = min(excl + rank, N_CONTENT - 1);   // matches jnp.clip
            g_col[r]  = bid * 64 + t;
            g_tval[r] = val;
        }
        if (bid == NCHUNK - 1 && t == 0)
            g_total = excl + cnt;
        __syncthreads();

        // completion: last prep block of THIS launch publishes g_done = L
        if (t == 0) {
            __threadfence();
            unsigned done = atomicAdd(&g_prep_ctr, 1u) + 1u;
            if (done == (unsigned)NCHUNK * L)
                g_done = L;
        }
    }

    // ======================= row phase (all 8256 blocks) ===================
    float4* row = out4 + (long long)bid * N_COL4;

    if (bid >= E_ROWS) {
        // tail row: zeros first (independent of prep)
        float4 z = make_float4(0.f, 0.f, 0.f, 0.f);
#pragma unroll
        for (int j = 0; j < 8; j++)
            __stcs(row + (t + j * 256), z);
        __syncthreads();

        if (t == 0) {
            while (g_done < L) __nanosleep(64);   // expected ~0 wait
            __threadfence();                       // acquire prep's writes
            int tr = bid - E_ROWS;
            if (tr < g_total)
                ((float*)row)[g_col[tr]] = g_tval[tr];
        }
        return;
    }

    // head/body rows need all prep chunks
    if (t == 0) {
        while (g_done < L) __nanosleep(64);
        __threadfence();
    }
    __syncthreads();

    if (bid == 0) {
#pragma unroll
        for (int j = 0; j < 8; j++) {
            int c4 = t + j * 256;
            row[c4] = g_head4[c4];
        }
    } else {
        const float4* xr = ((const float4*)x) + (long long)bid * N_COL4;
#pragma unroll
        for (int j = 0; j < 8; j++) {
            int c4 = t + j * 256;
            float4 v = xr[c4];              // L2-hot
            float4 m = g_mult4[c4];
            v.x *= m.x; v.y *= m.y; v.z *= m.z; v.w *= m.w;
            row[c4] = v;
        }
    }
}

// ---------------------------------------------------------------------------
extern "C" void kernel_launch(void* const* d_in, const int* in_sizes, int n_in,
                              void* d_out, int out_size) {
    const float* x = (const float*)d_in[0];
    float* out = (float*)d_out;
    fused_kernel<<<TOTAL_ROWS, 256>>>(x, (float4*)out);
}

// round 10
// speedup vs baseline: 1.0803x; 1.0803x over previous
#include <cuda_runtime.h>

// x: (64, 8, 32, 32) fp32. 1 center + 63 error rows, content = 8192 elements.
// Output = (1 + 63 + 8192) x 8192 = 270 MB.
#define N_CONTENT 8192
#define N_COL4    (N_CONTENT / 4)   // 2048
#define E_ROWS    64
#define NCHUNK    128               // prep blocks; 64 k's per chunk
#define PATCH_BLOCKS (N_CONTENT / 256)   // 32

// Scratch (__device__ globals; zero-initialized at module load)
__device__ float4             g_mult4[N_COL4];
__device__ float4             g_head4[N_COL4];
__device__ int                g_col[N_CONTENT];    // tail row r -> column k
__device__ float              g_tval[N_CONTENT];   // tail row r -> delta/2
__device__ int                g_total;             // number of crossings
__device__ unsigned long long g_pub[NCHUNK];       // (epoch<<32)|count
__device__ unsigned           g_prepep[NCHUNK];    // prep per-block launch counter
__device__ unsigned           g_patchep[PATCH_BLOCKS];
__device__ unsigned           g_prep_ctr;          // monotone completion count
__device__ volatile unsigned  g_done;              // = L once launch L's prep done

// ---------------------------------------------------------------------------
// K1: prep — per-k scalars + replay-safe cross-block prefix -> inverse map.
// ---------------------------------------------------------------------------
__global__ void prep_kernel(const float* __restrict__ x) {
    cudaTriggerProgrammaticLaunchCompletion();   // fill may launch immediately

    __shared__ float    s_err[4][64];
    __shared__ unsigned s_mask[2];
    __shared__ unsigned s_L;
    __shared__ int      s_excl;

    int t = threadIdx.x;
    int b = blockIdx.x;

    if (t == 0) {                          // launch epoch (replay-safe)
        unsigned L = g_prepep[b] + 1;
        g_prepep[b] = L;
        s_L = L;
    }

    int kk = t & 63;
    int sl = t >> 6;                       // e-slice 0..3 (16 rows each)
    {
        int k  = b * 64 + kk;
        int e0 = sl * 16 + (sl == 0 ? 1 : 0);   // skip center row
        int e1 = sl * 16 + 16;
        float p = 0.f;
#pragma unroll
        for (int e = e0; e < e1; e++)
            p += fabsf(x[e * N_CONTENT + k]);
        s_err[sl][kk] = p;
    }
    __syncthreads();
    unsigned L = s_L;

    int   flag = 0;
    float val  = 0.f;
    if (t < 64) {
        int k = b * 64 + t;
        float err = s_err[0][t] + s_err[1][t] + s_err[2][t] + s_err[3][t];
        float c = x[k];

        float upper = c + err;
        float lower = c - err;

        float cross  = (lower * upper < 0.f) ? 1.f : 0.f;
        float nonneg = (lower >= 0.f) ? 1.f : 0.f;

        // Reference-exact: lam = nonneg + cross*upper/(upper-lower), NaN -> 0.5
        float lam = nonneg + cross * (upper / (upper - lower));
        if (isnan(lam)) lam = 0.5f;

        float delta = fmaxf(-lam * lower, (1.f - lam) * upper);

        ((float*)g_mult4)[k] = lam * cross + nonneg;
        ((float*)g_head4)[k] = (delta * 0.5f + lam * c) * cross + c * nonneg;

        flag = (cross > 0.f) ? 1 : 0;
        val  = delta * 0.5f;

        unsigned bal = __ballot_sync(0xffffffffu, flag);
        if ((t & 31) == 0) s_mask[t >> 5] = bal;
    }
    __syncthreads();

    int cnt = __popc(s_mask[0]) + __popc(s_mask[1]);

    if (t == 0)
        atomicExch(&g_pub[b], ((unsigned long long)L << 32) | (unsigned)cnt);

    // warp 0: sum predecessor counts (32-wide overlapped polling)
    if (t < 32) {
        int sum = 0;
        for (int i = t; i < b; i += 32) {
            unsigned long long w2;
            do {
                w2 = *((volatile unsigned long long*)&g_pub[i]);
            } while ((unsigned)(w2 >> 32) != L);
            sum += (int)(w2 & 0xffffffffu);
        }
#pragma unroll
        for (int off = 16; off > 0; off >>= 1)
            sum += __shfl_down_sync(0xffffffffu, sum, off);
        if (t == 0) s_excl = sum;
    }
    __syncthreads();
    int excl = s_excl;

    if (t < 64 && flag) {
        unsigned m0 = s_mask[0], m1 = s_mask[1];
        int rank = (t < 32) ? __popc(m0 & ((1u << t) - 1u))
                            : __popc(m0) + __popc(m1 & ((1u << (t - 32)) - 1u));
        int r = min(excl + rank, N_CONTENT - 1);   // matches jnp.clip
        g_col[r]  = b * 64 + t;
        g_tval[r] = val;
    }
    if (b == NCHUNK - 1 && t == 0)
        g_total = excl + cnt;
    __syncthreads();

    // epoch-tagged completion flag (release)
    if (t == 0) {
        __threadfence();
        unsigned done = atomicAdd(&g_prep_ctr, 1u) + 1u;
        if (done == (unsigned)NCHUNK * L)
            g_done = L;
    }
}

// ---------------------------------------------------------------------------
// K2: fill — tail rows are PURE zero streaming (no prep dependency, retire
//     immediately); only head/body (64 blocks) gate on prep.
// ---------------------------------------------------------------------------
__global__ void __launch_bounds__(256) fill_kernel(
        const float4* __restrict__ x4, float4* __restrict__ out4) {
    int r = blockIdx.x;
    int t = threadIdx.x;
    float4* row = out4 + (long long)r * N_COL4;

    if (r >= E_ROWS) {
        float4 z = make_float4(0.f, 0.f, 0.f, 0.f);
#pragma unroll
        for (int j = 0; j < 8; j++)
            __stcs(row + (t + j * 256), z);
        cudaTriggerProgrammaticLaunchCompletion();   // near block end
        return;
    }

    cudaGridDependencySynchronize();        // head/body need prep results
    if (r == 0) {
#pragma unroll
        for (int j = 0; j < 8; j++) {
            int c4 = t + j * 256;
            row[c4] = g_head4[c4];
        }
    } else {
        const float4* xr = x4 + (long long)r * N_COL4;
#pragma unroll
        for (int j = 0; j < 8; j++) {
            int c4 = t + j * 256;
            float4 v = xr[c4];              // L2-hot
            float4 m = g_mult4[c4];
            v.x *= m.x; v.y *= m.y; v.z *= m.z; v.w *= m.w;
            row[c4] = v;
        }
    }
    cudaTriggerProgrammaticLaunchCompletion();
}

// ---------------------------------------------------------------------------
// K3: patch — after fill's grid completes, scatter the 8192 tail values.
// ---------------------------------------------------------------------------
__global__ void patch_kernel(float4* __restrict__ out4) {
    __shared__ unsigned s_L;
    int t = threadIdx.x;
    int b = blockIdx.x;

    if (t == 0) {
        unsigned L = g_patchep[b] + 1;      // replay-safe epoch
        g_patchep[b] = L;
        s_L = L;
    }
    cudaGridDependencySynchronize();        // ALL fill stores complete + visible
    __syncthreads();
    unsigned L = s_L;

    if (t == 0)
        while (g_done < L) __nanosleep(32); // prep ordering (expected 0 wait)
    __syncthreads();

    int r = b * 256 + t;
    if (r < g_total) {
        float* rowp = (float*)(out4 + (long long)(E_ROWS + r) * N_COL4);
        rowp[g_col[r]] = g_tval[r];
    }
}

// ---------------------------------------------------------------------------
extern "C" void kernel_launch(void* const* d_in, const int* in_sizes, int n_in,
                              void* d_out, int out_size) {
    const float* x = (const float*)d_in[0];
    float* out = (float*)d_out;

    prep_kernel<<<NCHUNK, 256>>>(x);

    cudaLaunchAttribute attr[1];
    attr[0].id = cudaLaunchAttributeProgrammaticStreamSerialization;
    attr[0].val.programmaticStreamSerializationAllowed = 1;

    cudaLaunchConfig_t cfg = {};
    cfg.blockDim = dim3(256, 1, 1);
    cfg.dynamicSmemBytes = 0;
    cfg.stream = 0;
    cfg.attrs = attr;
    cfg.numAttrs = 1;

    cfg.gridDim = dim3(E_ROWS + N_CONTENT, 1, 1);    // 8256
    cudaLaunchKernelEx(&cfg, fill_kernel, (const float4*)x, (float4*)out);

    cfg.gridDim = dim3(PATCH_BLOCKS, 1, 1);          // 32
    cudaLaunchKernelEx(&cfg, patch_kernel, (float4*)out);
}